// round 11
// baseline (speedup 1.0000x reference)
#include <cuda_runtime.h>
#include <cuda_bf16.h>
#include <cstdint>

#define BATCH  2048
#define TSTEPS 32
#define HDIM   1024
#define NGATE  4096
#define BK     32
#define LDS_T  40   // smem row stride in bf16 (80B: conflict-free ldmatrix, 16B aligned)

// ---------------- device scratch (static, allowed) ----------------
__device__ __align__(1024) __nv_bfloat16 g_Whi[NGATE * HDIM];   // reordered W_hh, bf16 hi
__device__ __align__(1024) __nv_bfloat16 g_Wlo[NGATE * HDIM];   // reordered W_hh, bf16 lo
__device__ __align__(1024) float g_bias[NGATE];                 // reordered b_ih + b_hh
__device__ __align__(1024) float g_wi0[NGATE];                  // reordered W_ih[:,0]
__device__ __align__(1024) float g_wi1[NGATE];                  // reordered W_ih[:,1]
__device__ __align__(1024) float g_h[BATCH * HDIM];             // hidden state fp32
__device__ __align__(1024) float g_c[BATCH * HDIM];             // cell state fp32
__device__ __align__(1024) float g_pred[BATCH];                 // previous prediction
// Ping-pong h split buffers: step t READS buf[t&1], WRITES buf[t&1 ^ 1].
__device__ __align__(1024) __nv_bfloat16 g_hhi[2][BATCH * HDIM];
__device__ __align__(1024) __nv_bfloat16 g_hlo[2][BATCH * HDIM];

// ---------------- math helpers ----------------
static __device__ __forceinline__ float sigm(float x) {
    return 1.0f / (1.0f + __expf(-x));
}
static __device__ __forceinline__ float tanhx(float x) {
    return 1.0f - 2.0f / (__expf(2.0f * x) + 1.0f);
}

// ---------------- mma/ldmatrix wrappers (sm_80-era: valid on compute_103 base) ----
static __device__ __forceinline__ void ldmx4(uint32_t* r, uint32_t addr) {
    asm volatile("ldmatrix.sync.aligned.m8n8.x4.shared.b16 {%0,%1,%2,%3}, [%4];"
                 : "=r"(r[0]), "=r"(r[1]), "=r"(r[2]), "=r"(r[3]) : "r"(addr));
}
static __device__ __forceinline__ void ldmx2(uint32_t* r, uint32_t addr) {
    asm volatile("ldmatrix.sync.aligned.m8n8.x2.shared.b16 {%0,%1}, [%2];"
                 : "=r"(r[0]), "=r"(r[1]) : "r"(addr));
}
static __device__ __forceinline__ void mma16816(float* c, const uint32_t* a, const uint32_t* b) {
    asm volatile("mma.sync.aligned.m16n8k16.row.col.f32.bf16.bf16.f32 "
                 "{%0,%1,%2,%3}, {%4,%5,%6,%7}, {%8,%9}, {%0,%1,%2,%3};"
                 : "+f"(c[0]), "+f"(c[1]), "+f"(c[2]), "+f"(c[3])
                 : "r"(a[0]), "r"(a[1]), "r"(a[2]), "r"(a[3]), "r"(b[0]), "r"(b[1]));
}

// ---------------- prep kernels ----------------
// reorder: rn = unit*4 + gate  ->  original row r0 = gate*HDIM + unit
__global__ void prep_W(const float* __restrict__ Whh) {
    int idx = blockIdx.x * 256 + threadIdx.x;        // over NGATE*HDIM
    int rn = idx >> 10;
    int k  = idx & 1023;
    int gate = rn & 3;
    int unit = rn >> 2;
    float w = Whh[(size_t)(gate * HDIM + unit) * HDIM + k];
    __nv_bfloat16 hi = __float2bfloat16(w);
    g_Whi[idx] = hi;
    g_Wlo[idx] = __float2bfloat16(w - __bfloat162float(hi));
}

__global__ void prep_vec(const float* __restrict__ Wih,
                         const float* __restrict__ bih,
                         const float* __restrict__ bhh) {
    int rn = blockIdx.x * 256 + threadIdx.x;
    if (rn < NGATE) {
        int r0 = (rn & 3) * HDIM + (rn >> 2);
        g_bias[rn] = bih[r0] + bhh[r0];
        g_wi0[rn]  = Wih[r0 * 2 + 0];
        g_wi1[rn]  = Wih[r0 * 2 + 1];
    }
}

__global__ void prep_state(const float* __restrict__ hidden,
                           const float* __restrict__ cell) {
    int i = blockIdx.x * 256 + threadIdx.x;          // over BATCH*HDIM
    float h = hidden[i];
    __nv_bfloat16 hi = __float2bfloat16(h);
    g_h[i]      = h;
    g_hhi[0][i] = hi;
    g_hlo[0][i] = __float2bfloat16(h - __bfloat162float(hi));
    g_c[i]      = cell[i];
    if (i < BATCH) g_pred[i] = 0.0f;
}

// ---------------- main step: bf16 3-split mma.sync GEMM + fused LSTM cell ------
// grid (16 batch tiles, 32 gate tiles), 256 threads (8 warps: 2 M x 4 N).
// CTA: gates[128 batch x 128 rn rows] = h@Whh^T (3-split), then cell update
// for 128 batch x 32 units.
__global__ void __launch_bounds__(256, 2)
lstm_step(const float* __restrict__ fd, int t) {
    __shared__ __align__(16) __nv_bfloat16 sAhi[128 * LDS_T];
    __shared__ __align__(16) __nv_bfloat16 sAlo[128 * LDS_T];
    __shared__ __align__(16) __nv_bfloat16 sBhi[128 * LDS_T];
    __shared__ __align__(16) __nv_bfloat16 sBlo[128 * LDS_T];
    __shared__ __align__(16) float sBias[128];
    __shared__ __align__(16) float sW0[128];
    __shared__ __align__(16) float sW1[128];
    __shared__ float sPred[128];
    __shared__ float sFd[128];

    const int tid  = threadIdx.x;
    const int lane = tid & 31;
    const int wid  = tid >> 5;
    const int wr   = wid >> 2;   // warp M row (0-1)
    const int wn   = wid & 3;    // warp N col (0-3)
    const int mt = blockIdx.x;   // batch tile
    const int nt = blockIdx.y;   // gate tile (128 rn rows = 32 units)
    const int rb = t & 1;
    const int wbuf = rb ^ 1;

    if (tid < 128) {
        int r = nt * 128 + tid;
        sBias[tid] = g_bias[r];
        sW0[tid]   = g_wi0[r];
        sW1[tid]   = g_wi1[r];
        int b = mt * 128 + tid;
        sPred[tid] = g_pred[b];
        sFd[tid]   = fd[(size_t)b * TSTEPS + t];
    }

    const __nv_bfloat16* aHi = g_hhi[rb] + (size_t)(mt * 128) * HDIM;
    const __nv_bfloat16* aLo = g_hlo[rb] + (size_t)(mt * 128) * HDIM;
    const __nv_bfloat16* bHi = g_Whi + (size_t)(nt * 128) * HDIM;
    const __nv_bfloat16* bLo = g_Wlo + (size_t)(nt * 128) * HDIM;

    float acc[4][4][4];
#pragma unroll
    for (int i = 0; i < 4; ++i)
#pragma unroll
        for (int j = 0; j < 4; ++j)
#pragma unroll
            for (int v = 0; v < 4; ++v) acc[i][j][v] = 0.0f;

    // ldmatrix smem addresses (lane-dependent parts precomputed)
    const uint32_t aAhi = (uint32_t)__cvta_generic_to_shared(sAhi);
    const uint32_t aAlo = (uint32_t)__cvta_generic_to_shared(sAlo);
    const uint32_t aBhi = (uint32_t)__cvta_generic_to_shared(sBhi);
    const uint32_t aBlo = (uint32_t)__cvta_generic_to_shared(sBlo);
    const uint32_t offA = ((uint32_t)(lane & 15) * LDS_T + (lane >> 4) * 8) * 2;
    const uint32_t offB = ((uint32_t)(lane & 7) * LDS_T + (lane >> 3) * 8) * 2;

    __syncthreads();   // sPred/sBias ready (also orders first smem-tile writes)

    for (int kc = 0; kc < 32; ++kc) {
        const int k0 = kc * BK;
        // Full-tile load: 128 rows x 32 cols bf16 per array.
        // 2 passes x 256 threads x 8 elems: e = tid+256u -> row=e>>2, quarter=e&3.
        // (Round-10 version loaded only cols 0-15 — k16=1 MMAs read garbage.)
#pragma unroll
        for (int u = 0; u < 2; ++u) {
            const int e   = tid + u * 256;    // 0..511
            const int row = e >> 2;
            const int q   = e & 3;
            const size_t gsrc = (size_t)row * HDIM + k0 + q * 8;
            const uint32_t sdst = row * LDS_T + q * 8;
            *reinterpret_cast<uint4*>(sAhi + sdst) = *reinterpret_cast<const uint4*>(aHi + gsrc);
            *reinterpret_cast<uint4*>(sAlo + sdst) = *reinterpret_cast<const uint4*>(aLo + gsrc);
            *reinterpret_cast<uint4*>(sBhi + sdst) = *reinterpret_cast<const uint4*>(bHi + gsrc);
            *reinterpret_cast<uint4*>(sBlo + sdst) = *reinterpret_cast<const uint4*>(bLo + gsrc);
        }
        __syncthreads();

#pragma unroll
        for (int k16 = 0; k16 < 2; ++k16) {
            const uint32_t kb = (uint32_t)(k16 * 16) * 2;
            uint32_t bh[4][2], bl[4][2], af[4][4];
#pragma unroll
            for (int ni = 0; ni < 4; ++ni) {
                uint32_t ro = (uint32_t)((wn * 32 + ni * 8) * LDS_T) * 2;
                ldmx2(bh[ni], aBhi + ro + kb + offB);
                ldmx2(bl[ni], aBlo + ro + kb + offB);
            }
#pragma unroll
            for (int mi = 0; mi < 4; ++mi) {
                uint32_t ro = (uint32_t)((wr * 64 + mi * 16) * LDS_T) * 2;
                ldmx4(af[mi], aAhi + ro + kb + offA);
            }
#pragma unroll
            for (int mi = 0; mi < 4; ++mi)
#pragma unroll
                for (int ni = 0; ni < 4; ++ni) {
                    mma16816(acc[mi][ni], af[mi], bh[ni]);   // hi*hi
                    mma16816(acc[mi][ni], af[mi], bl[ni]);   // hi*lo
                }
#pragma unroll
            for (int mi = 0; mi < 4; ++mi) {
                uint32_t ro = (uint32_t)((wr * 64 + mi * 16) * LDS_T) * 2;
                ldmx4(af[mi], aAlo + ro + kb + offA);
            }
#pragma unroll
            for (int mi = 0; mi < 4; ++mi)
#pragma unroll
                for (int ni = 0; ni < 4; ++ni)
                    mma16816(acc[mi][ni], af[mi], bh[ni]);   // lo*hi
        }
        __syncthreads();
    }

    // ---------------- epilogue: LSTM cell ----------------
    // D lane layout (m16n8k16): d0,d1 = (row=lane>>2, col=2(lane&3),+1); d2,d3 = row+8.
    // gate = col&3 (rn = unit*4+gate); adjacent-lane shfl_xor(1) exchange gives each
    // lane all 4 gates of one unit for one batch row.
    const int p     = lane & 3;
    const int rquad = lane >> 2;
#pragma unroll
    for (int mi = 0; mi < 4; ++mi) {
#pragma unroll
        for (int ni = 0; ni < 4; ++ni) {
            float d0 = acc[mi][ni][0], d1 = acc[mi][ni][1];
            float d2 = acc[mi][ni][2], d3 = acc[mi][ni][3];
            float t0 = __shfl_xor_sync(0xffffffffu, d0, 1);
            float t1 = __shfl_xor_sync(0xffffffffu, d1, 1);
            float t2 = __shfl_xor_sync(0xffffffffu, d2, 1);
            float t3 = __shfl_xor_sync(0xffffffffu, d3, 1);
            float gi, gf, gg, go;
            int rowo;
            if ((p & 1) == 0) { gi = d0; gf = d1; gg = t0; go = t1; rowo = rquad; }
            else             { gi = t2; gf = t3; gg = d2; go = d3; rowo = rquad + 8; }
            const int ju = wn * 8 + ni * 2 + (p >> 1);      // local unit 0..31
            const int bl_ = wr * 64 + mi * 16 + rowo;       // local batch row 0..127
            float4 bs = *reinterpret_cast<const float4*>(&sBias[ju * 4]);
            float4 w0 = *reinterpret_cast<const float4*>(&sW0[ju * 4]);
            float4 w1 = *reinterpret_cast<const float4*>(&sW1[ju * 4]);
            const float pp = sPred[bl_];
            const float fv = sFd[bl_];
            gi += bs.x + pp * w0.x + fv * w1.x;
            gf += bs.y + pp * w0.y + fv * w1.y;
            gg += bs.z + pp * w0.z + fv * w1.z;
            go += bs.w + pp * w0.w + fv * w1.w;
            const size_t off = (size_t)(mt * 128 + bl_) * HDIM + nt * 32 + ju;
            float cold = g_c[off];
            float cn = sigm(gf) * cold + sigm(gi) * tanhx(gg);
            float hn = sigm(go) * tanhx(cn);
            g_c[off] = cn;
            g_h[off] = hn;
            __nv_bfloat16 hi = __float2bfloat16(hn);
            g_hhi[wbuf][off] = hi;
            g_hlo[wbuf][off] = __float2bfloat16(hn - __bfloat162float(hi));
        }
    }
}

// ---------------- prediction + output ----------------
__global__ void pred_out(const float* __restrict__ fcW, const float* __restrict__ fcb,
                         float* __restrict__ out, int t) {
    int wid = threadIdx.x >> 5, lane = threadIdx.x & 31;
    int b = blockIdx.x * 8 + wid;
    const float* hr = g_h + (size_t)b * HDIM;
    float s = 0.0f;
#pragma unroll 8
    for (int k = lane; k < HDIM; k += 32) s += hr[k] * fcW[k];
#pragma unroll
    for (int o = 16; o; o >>= 1) s += __shfl_xor_sync(0xffffffffu, s, o);
    if (lane == 0) {
        float p = s + fcb[0];
        g_pred[b] = p;
        out[(size_t)b * TSTEPS + t] = p;
    }
}

// ---------------- launch ----------------
extern "C" void kernel_launch(void* const* d_in, const int* in_sizes, int n_in,
                              void* d_out, int out_size) {
    const float* fd     = (const float*)d_in[0];
    const float* hidden = (const float*)d_in[1];
    const float* cell   = (const float*)d_in[2];
    const float* Wih    = (const float*)d_in[3];
    const float* Whh    = (const float*)d_in[4];
    const float* bih    = (const float*)d_in[5];
    const float* bhh    = (const float*)d_in[6];
    const float* fcW    = (const float*)d_in[7];
    const float* fcb    = (const float*)d_in[8];
    float* out = (float*)d_out;

    prep_W<<<(NGATE * HDIM) / 256, 256>>>(Whh);
    prep_vec<<<NGATE / 256, 256>>>(Wih, bih, bhh);
    prep_state<<<(BATCH * HDIM) / 256, 256>>>(hidden, cell);

    for (int t = 0; t < TSTEPS; ++t) {
        lstm_step<<<dim3(16, 32), 256>>>(fd, t);
        pred_out<<<BATCH / 8, 256>>>(fcW, fcb, out, t);
    }
}

// round 12
// speedup vs baseline: 1.0930x; 1.0930x over previous
#include <cuda_runtime.h>
#include <cuda_bf16.h>
#include <cstdint>

#define BATCH  2048
#define TSTEPS 32
#define HDIM   1024
#define NGATE  4096
#define BK     32
#define LDS_T  40   // smem row stride in bf16 (80B: conflict-free ldmatrix, 16B aligned)

#define TILE_B   (128 * LDS_T * 2)   // 10240 B per tile
#define STAGE_B  (4 * TILE_B)        // 40960 B per stage (Ahi, Alo, Bhi, Blo)
#define OFF_BIAS (2 * STAGE_B)       // 81920
#define OFF_W0   (OFF_BIAS + 512)
#define OFF_W1   (OFF_W0 + 512)
#define OFF_PRED (OFF_W1 + 512)
#define OFF_FD   (OFF_PRED + 512)
#define SMEM_TOT (OFF_FD + 512)      // 84480 B

// ---------------- device scratch (static, allowed) ----------------
__device__ __align__(1024) __nv_bfloat16 g_Whi[NGATE * HDIM];   // reordered W_hh, bf16 hi
__device__ __align__(1024) __nv_bfloat16 g_Wlo[NGATE * HDIM];   // reordered W_hh, bf16 lo
__device__ __align__(1024) float g_bias[NGATE];                 // reordered b_ih + b_hh
__device__ __align__(1024) float g_wi0[NGATE];                  // reordered W_ih[:,0]
__device__ __align__(1024) float g_wi1[NGATE];                  // reordered W_ih[:,1]
__device__ __align__(1024) float g_h[BATCH * HDIM];             // hidden state fp32
__device__ __align__(1024) float g_c[BATCH * HDIM];             // cell state fp32
__device__ __align__(1024) float g_pred[BATCH];                 // previous prediction
// Ping-pong h split buffers: step t READS buf[t&1], WRITES buf[t&1 ^ 1].
__device__ __align__(1024) __nv_bfloat16 g_hhi[2][BATCH * HDIM];
__device__ __align__(1024) __nv_bfloat16 g_hlo[2][BATCH * HDIM];

// ---------------- math helpers ----------------
static __device__ __forceinline__ float sigm(float x) {
    return 1.0f / (1.0f + __expf(-x));
}
static __device__ __forceinline__ float tanhx(float x) {
    return 1.0f - 2.0f / (__expf(2.0f * x) + 1.0f);
}

// ---------------- mma/ldmatrix/cp.async wrappers (sm_80-era, valid on compute_103) ----
static __device__ __forceinline__ void ldmx4(uint32_t* r, uint32_t addr) {
    asm volatile("ldmatrix.sync.aligned.m8n8.x4.shared.b16 {%0,%1,%2,%3}, [%4];"
                 : "=r"(r[0]), "=r"(r[1]), "=r"(r[2]), "=r"(r[3]) : "r"(addr));
}
static __device__ __forceinline__ void ldmx2(uint32_t* r, uint32_t addr) {
    asm volatile("ldmatrix.sync.aligned.m8n8.x2.shared.b16 {%0,%1}, [%2];"
                 : "=r"(r[0]), "=r"(r[1]) : "r"(addr));
}
static __device__ __forceinline__ void mma16816(float* c, const uint32_t* a, const uint32_t* b) {
    asm volatile("mma.sync.aligned.m16n8k16.row.col.f32.bf16.bf16.f32 "
                 "{%0,%1,%2,%3}, {%4,%5,%6,%7}, {%8,%9}, {%0,%1,%2,%3};"
                 : "+f"(c[0]), "+f"(c[1]), "+f"(c[2]), "+f"(c[3])
                 : "r"(a[0]), "r"(a[1]), "r"(a[2]), "r"(a[3]), "r"(b[0]), "r"(b[1]));
}
static __device__ __forceinline__ void cpa16(uint32_t sdst, const void* gsrc) {
    asm volatile("cp.async.cg.shared.global [%0], [%1], 16;" :: "r"(sdst), "l"(gsrc));
}

// ---------------- prep kernels ----------------
// reorder: rn = unit*4 + gate  ->  original row r0 = gate*HDIM + unit
__global__ void prep_W(const float* __restrict__ Whh) {
    int idx = blockIdx.x * 256 + threadIdx.x;        // over NGATE*HDIM
    int rn = idx >> 10;
    int k  = idx & 1023;
    int gate = rn & 3;
    int unit = rn >> 2;
    float w = Whh[(size_t)(gate * HDIM + unit) * HDIM + k];
    __nv_bfloat16 hi = __float2bfloat16(w);
    g_Whi[idx] = hi;
    g_Wlo[idx] = __float2bfloat16(w - __bfloat162float(hi));
}

__global__ void prep_vec(const float* __restrict__ Wih,
                         const float* __restrict__ bih,
                         const float* __restrict__ bhh) {
    int rn = blockIdx.x * 256 + threadIdx.x;
    if (rn < NGATE) {
        int r0 = (rn & 3) * HDIM + (rn >> 2);
        g_bias[rn] = bih[r0] + bhh[r0];
        g_wi0[rn]  = Wih[r0 * 2 + 0];
        g_wi1[rn]  = Wih[r0 * 2 + 1];
    }
}

__global__ void prep_state(const float* __restrict__ hidden,
                           const float* __restrict__ cell) {
    int i = blockIdx.x * 256 + threadIdx.x;          // over BATCH*HDIM
    float h = hidden[i];
    __nv_bfloat16 hi = __float2bfloat16(h);
    g_h[i]      = h;
    g_hhi[0][i] = hi;
    g_hlo[0][i] = __float2bfloat16(h - __bfloat162float(hi));
    g_c[i]      = cell[i];
    if (i < BATCH) g_pred[i] = 0.0f;
}

// ---------------- main step: bf16 3-split mma.sync GEMM + fused LSTM cell ------
// grid (16 batch tiles, 32 gate tiles), 256 threads (8 warps: 2 M x 4 N).
// 2-stage cp.async double-buffered K pipeline (BK=32, 32 chunks).
__global__ void __launch_bounds__(256, 2)
lstm_step(const float* __restrict__ fd, int t) {
    extern __shared__ char dynsmem[];
    const uint32_t sb = (uint32_t)__cvta_generic_to_shared(dynsmem);

    const int tid  = threadIdx.x;
    const int lane = tid & 31;
    const int wid  = tid >> 5;
    const int wr   = wid >> 2;   // warp M row (0-1)
    const int wn   = wid & 3;    // warp N col (0-3)
    const int mt = blockIdx.x;   // batch tile
    const int nt = blockIdx.y;   // gate tile (128 rn rows = 32 units)
    const int rb = t & 1;
    const int wbuf = rb ^ 1;

    float* sBias = (float*)(dynsmem + OFF_BIAS);
    float* sW0   = (float*)(dynsmem + OFF_W0);
    float* sW1   = (float*)(dynsmem + OFF_W1);
    float* sPred = (float*)(dynsmem + OFF_PRED);
    float* sFd   = (float*)(dynsmem + OFF_FD);

    if (tid < 128) {
        int r = nt * 128 + tid;
        sBias[tid] = g_bias[r];
        sW0[tid]   = g_wi0[r];
        sW1[tid]   = g_wi1[r];
        int b = mt * 128 + tid;
        sPred[tid] = g_pred[b];
        sFd[tid]   = fd[(size_t)b * TSTEPS + t];
    }

    const __nv_bfloat16* aHi = g_hhi[rb] + (size_t)(mt * 128) * HDIM;
    const __nv_bfloat16* aLo = g_hlo[rb] + (size_t)(mt * 128) * HDIM;
    const __nv_bfloat16* bHi = g_Whi + (size_t)(nt * 128) * HDIM;
    const __nv_bfloat16* bLo = g_Wlo + (size_t)(nt * 128) * HDIM;

    // per-thread load geometry: 2 passes x 8 bf16 (16B) per array
    const int e0row = tid >> 2;          // pass0 row 0..63
    const int e0q   = tid & 3;
    // pass1: e = tid + 256 -> row = 64 + (tid>>2), same q

    float acc[4][4][4];
#pragma unroll
    for (int i = 0; i < 4; ++i)
#pragma unroll
        for (int j = 0; j < 4; ++j)
#pragma unroll
            for (int v = 0; v < 4; ++v) acc[i][j][v] = 0.0f;

    const uint32_t offA = ((uint32_t)(lane & 15) * LDS_T + (lane >> 4) * 8) * 2;
    const uint32_t offB = ((uint32_t)(lane & 7) * LDS_T + (lane >> 3) * 8) * 2;

    // ---- pipeline prologue: stage 0 <- kc 0 ----
    {
        const int k0 = 0;
#pragma unroll
        for (int u = 0; u < 2; ++u) {
            const int row = e0row + u * 64;
            const size_t gsrc = (size_t)row * HDIM + k0 + e0q * 8;
            const uint32_t sdst = sb + (uint32_t)(row * LDS_T + e0q * 8) * 2;
            cpa16(sdst + 0 * TILE_B, aHi + gsrc);
            cpa16(sdst + 1 * TILE_B, aLo + gsrc);
            cpa16(sdst + 2 * TILE_B, bHi + gsrc);
            cpa16(sdst + 3 * TILE_B, bLo + gsrc);
        }
        asm volatile("cp.async.commit_group;");
    }

    for (int kc = 0; kc < 32; ++kc) {
        const uint32_t cs = (uint32_t)(kc & 1);
        // prefetch kc+1 into the other stage
        if (kc + 1 < 32) {
            const int k0n = (kc + 1) * BK;
            const uint32_t stg = sb + (cs ^ 1u) * STAGE_B;
#pragma unroll
            for (int u = 0; u < 2; ++u) {
                const int row = e0row + u * 64;
                const size_t gsrc = (size_t)row * HDIM + k0n + e0q * 8;
                const uint32_t sdst = stg + (uint32_t)(row * LDS_T + e0q * 8) * 2;
                cpa16(sdst + 0 * TILE_B, aHi + gsrc);
                cpa16(sdst + 1 * TILE_B, aLo + gsrc);
                cpa16(sdst + 2 * TILE_B, bHi + gsrc);
                cpa16(sdst + 3 * TILE_B, bLo + gsrc);
            }
            asm volatile("cp.async.commit_group;");
            asm volatile("cp.async.wait_group 1;");   // current stage complete
        } else {
            asm volatile("cp.async.wait_group 0;");
        }
        __syncthreads();   // current stage visible to all warps

        const uint32_t aAhi = sb + cs * STAGE_B + 0 * TILE_B;
        const uint32_t aAlo = aAhi + TILE_B;
        const uint32_t aBhi = aAhi + 2 * TILE_B;
        const uint32_t aBlo = aAhi + 3 * TILE_B;

#pragma unroll
        for (int k16 = 0; k16 < 2; ++k16) {
            const uint32_t kb = (uint32_t)(k16 * 16) * 2;
            uint32_t bh[4][2], bl[4][2], af[4][4];
#pragma unroll
            for (int ni = 0; ni < 4; ++ni) {
                uint32_t ro = (uint32_t)((wn * 32 + ni * 8) * LDS_T) * 2;
                ldmx2(bh[ni], aBhi + ro + kb + offB);
                ldmx2(bl[ni], aBlo + ro + kb + offB);
            }
#pragma unroll
            for (int mi = 0; mi < 4; ++mi) {
                uint32_t ro = (uint32_t)((wr * 64 + mi * 16) * LDS_T) * 2;
                ldmx4(af[mi], aAhi + ro + kb + offA);
            }
#pragma unroll
            for (int mi = 0; mi < 4; ++mi)
#pragma unroll
                for (int ni = 0; ni < 4; ++ni) {
                    mma16816(acc[mi][ni], af[mi], bh[ni]);   // hi*hi
                    mma16816(acc[mi][ni], af[mi], bl[ni]);   // hi*lo
                }
#pragma unroll
            for (int mi = 0; mi < 4; ++mi) {
                uint32_t ro = (uint32_t)((wr * 64 + mi * 16) * LDS_T) * 2;
                ldmx4(af[mi], aAlo + ro + kb + offA);
            }
#pragma unroll
            for (int mi = 0; mi < 4; ++mi)
#pragma unroll
                for (int ni = 0; ni < 4; ++ni)
                    mma16816(acc[mi][ni], af[mi], bh[ni]);   // lo*hi
        }
        __syncthreads();   // done with this stage before it is refilled at kc+2
    }

    // ---------------- epilogue: LSTM cell ----------------
    // D lane layout (m16n8k16): d0,d1 = (row=lane>>2, col=2(lane&3),+1); d2,d3 = row+8.
    // gate = col&3 (rn = unit*4+gate); adjacent-lane shfl_xor(1) exchange gives each
    // lane all 4 gates of one unit for one batch row.
    const int p     = lane & 3;
    const int rquad = lane >> 2;
#pragma unroll
    for (int mi = 0; mi < 4; ++mi) {
#pragma unroll
        for (int ni = 0; ni < 4; ++ni) {
            float d0 = acc[mi][ni][0], d1 = acc[mi][ni][1];
            float d2 = acc[mi][ni][2], d3 = acc[mi][ni][3];
            float t0 = __shfl_xor_sync(0xffffffffu, d0, 1);
            float t1 = __shfl_xor_sync(0xffffffffu, d1, 1);
            float t2 = __shfl_xor_sync(0xffffffffu, d2, 1);
            float t3 = __shfl_xor_sync(0xffffffffu, d3, 1);
            float gi, gf, gg, go;
            int rowo;
            if ((p & 1) == 0) { gi = d0; gf = d1; gg = t0; go = t1; rowo = rquad; }
            else             { gi = t2; gf = t3; gg = d2; go = d3; rowo = rquad + 8; }
            const int ju = wn * 8 + ni * 2 + (p >> 1);      // local unit 0..31
            const int bl_ = wr * 64 + mi * 16 + rowo;       // local batch row 0..127
            float4 bs = *reinterpret_cast<const float4*>(&sBias[ju * 4]);
            float4 w0 = *reinterpret_cast<const float4*>(&sW0[ju * 4]);
            float4 w1 = *reinterpret_cast<const float4*>(&sW1[ju * 4]);
            const float pp = sPred[bl_];
            const float fv = sFd[bl_];
            gi += bs.x + pp * w0.x + fv * w1.x;
            gf += bs.y + pp * w0.y + fv * w1.y;
            gg += bs.z + pp * w0.z + fv * w1.z;
            go += bs.w + pp * w0.w + fv * w1.w;
            const size_t off = (size_t)(mt * 128 + bl_) * HDIM + nt * 32 + ju;
            float cold = g_c[off];
            float cn = sigm(gf) * cold + sigm(gi) * tanhx(gg);
            float hn = sigm(go) * tanhx(cn);
            g_c[off] = cn;
            g_h[off] = hn;
            __nv_bfloat16 hi = __float2bfloat16(hn);
            g_hhi[wbuf][off] = hi;
            g_hlo[wbuf][off] = __float2bfloat16(hn - __bfloat162float(hi));
        }
    }
}

// ---------------- prediction + output ----------------
__global__ void pred_out(const float* __restrict__ fcW, const float* __restrict__ fcb,
                         float* __restrict__ out, int t) {
    int wid = threadIdx.x >> 5, lane = threadIdx.x & 31;
    int b = blockIdx.x * 8 + wid;
    const float* hr = g_h + (size_t)b * HDIM;
    float s = 0.0f;
#pragma unroll 8
    for (int k = lane; k < HDIM; k += 32) s += hr[k] * fcW[k];
#pragma unroll
    for (int o = 16; o; o >>= 1) s += __shfl_xor_sync(0xffffffffu, s, o);
    if (lane == 0) {
        float p = s + fcb[0];
        g_pred[b] = p;
        out[(size_t)b * TSTEPS + t] = p;
    }
}

// ---------------- launch ----------------
extern "C" void kernel_launch(void* const* d_in, const int* in_sizes, int n_in,
                              void* d_out, int out_size) {
    const float* fd     = (const float*)d_in[0];
    const float* hidden = (const float*)d_in[1];
    const float* cell   = (const float*)d_in[2];
    const float* Wih    = (const float*)d_in[3];
    const float* Whh    = (const float*)d_in[4];
    const float* bih    = (const float*)d_in[5];
    const float* bhh    = (const float*)d_in[6];
    const float* fcW    = (const float*)d_in[7];
    const float* fcb    = (const float*)d_in[8];
    float* out = (float*)d_out;

    cudaFuncSetAttribute(lstm_step, cudaFuncAttributeMaxDynamicSharedMemorySize, SMEM_TOT);

    prep_W<<<(NGATE * HDIM) / 256, 256>>>(Whh);
    prep_vec<<<NGATE / 256, 256>>>(Wih, bih, bhh);
    prep_state<<<(BATCH * HDIM) / 256, 256>>>(hidden, cell);

    for (int t = 0; t < TSTEPS; ++t) {
        lstm_step<<<dim3(16, 32), 256, SMEM_TOT>>>(fd, t);
        pred_out<<<BATCH / 8, 256>>>(fcW, fcb, out, t);
    }
}